// round 7
// baseline (speedup 1.0000x reference)
#include <cuda_runtime.h>
#include <cstdint>

// Problem constants
#define T_STEPS 1024
#define BATCH   32
#define DIM     1024
#define NH      64
#define NTOT    256                 // 4 * NH (k | v | q | ax)
#define M_TOTAL (T_STEPS * BATCH)   // 32768

// Scratch: projections Y[m][256], m = t*BATCH+b  (32 MB)
__device__ float g_y[(size_t)M_TOTAL * NTOT];
// Precomputed per-(t,b) dot scalars, 12 floats per slot T:
//  [0..3]: KK2(T+1), KK3(T+1), KK4(T+1), KK1(T)
//  [4..7]: KQ2(T+1), KQ3(T+1), KQ4(T+1), KQ1(T)
//  [8]   : KQ0(T)
__device__ float g_pc[(size_t)M_TOTAL * 12];

// ---------------- GEMM: 128-thr blocks, 2 blocks/SM, block tile 128x128 ----------------
#define BM 128
#define BN 128
#define BK 16
#define STAGES 3
#define XS_STRIDE 20
#define X_TILE_F (BM * XS_STRIDE)          // 2560
#define W_TILE_F (BN * XS_STRIDE)          // 2560
#define STAGE_F  (X_TILE_F + W_TILE_F)     // 5120
#define SMEM_BYTES (STAGES * STAGE_F * 4)  // 61440

__device__ __forceinline__ void cp_async16(uint32_t saddr, const void* gptr) {
    asm volatile("cp.async.cg.shared.global [%0], [%1], 16;\n" :: "r"(saddr), "l"(gptr));
}
__device__ __forceinline__ uint32_t f2tf32(float f) {
    uint32_t r;
    asm("cvt.rna.tf32.f32 %0, %1;" : "=r"(r) : "f"(f));
    return r;
}
__device__ __forceinline__ void mma_tf32(float* c, const uint32_t* a, const uint32_t* b) {
    asm volatile(
        "mma.sync.aligned.m16n8k8.row.col.f32.tf32.tf32.f32 "
        "{%0,%1,%2,%3}, {%4,%5,%6,%7}, {%8,%9}, {%0,%1,%2,%3};"
        : "+f"(c[0]), "+f"(c[1]), "+f"(c[2]), "+f"(c[3])
        : "r"(a[0]), "r"(a[1]), "r"(a[2]), "r"(a[3]), "r"(b[0]), "r"(b[1]));
}

__global__ __launch_bounds__(128, 2)
void proj_gemm(const float* __restrict__ X,
               const float* __restrict__ Wk, const float* __restrict__ Wv,
               const float* __restrict__ Wq, const float* __restrict__ Wa)
{
    extern __shared__ float smem[];
    const int tid = threadIdx.x;
    const int m0  = blockIdx.x * BM;
    const int h   = blockIdx.y;          // n-half: columns h*128 .. h*128+127

    const float* wptr[4] = {Wk, Wv, Wq, Wa};

    // X: 4 float4/thread/stage (2048 floats)
    const float* xg[4];
    uint32_t xs_off[4];
#pragma unroll
    for (int l = 0; l < 4; l++) {
        int f = tid + l * 128;
        int row = f >> 2, c4 = f & 3;
        xg[l] = X + (size_t)(m0 + row) * DIM + c4 * 4;
        xs_off[l] = (uint32_t)(row * XS_STRIDE + c4 * 4);
    }
    // W: 4 float4/thread/stage (rows h*128 .. h*128+127 of the stacked W)
    const float* wg[4];
    uint32_t ws_off[4];
#pragma unroll
    for (int l = 0; l < 4; l++) {
        int f = tid + l * 128;
        int row = f >> 2, c4 = f & 3;
        int gr = h * BN + row;           // global stacked-W row 0..255
        wg[l] = wptr[gr >> 6] + (size_t)(gr & 63) * DIM + c4 * 4;
        ws_off[l] = (uint32_t)(X_TILE_F + row * XS_STRIDE + c4 * 4);
    }
    uint32_t smem_base = (uint32_t)__cvta_generic_to_shared(smem);

    const int lane = tid & 31;
    const int w    = tid >> 5;    // 0..3
    const int g    = lane >> 2;
    const int q    = lane & 3;
    const int wm   = w >> 1;      // 0..1 : 64-row slab
    const int wn   = w & 1;       // 0..1 : 64-col slab

    float acc[4][8][4];
#pragma unroll
    for (int mi = 0; mi < 4; mi++)
#pragma unroll
        for (int ni = 0; ni < 8; ni++)
#pragma unroll
            for (int r = 0; r < 4; r++) acc[mi][ni][r] = 0.0f;

    const int NITER = DIM / BK;

#pragma unroll
    for (int s = 0; s < STAGES - 1; s++) {
        uint32_t sb = smem_base + (uint32_t)((s % STAGES) * STAGE_F * 4);
        int koff = s * BK;
#pragma unroll
        for (int l = 0; l < 4; l++) cp_async16(sb + xs_off[l] * 4, xg[l] + koff);
#pragma unroll
        for (int l = 0; l < 4; l++) cp_async16(sb + ws_off[l] * 4, wg[l] + koff);
        asm volatile("cp.async.commit_group;\n");
    }

    for (int k = 0; k < NITER; k++) {
        asm volatile("cp.async.wait_group %0;\n" :: "n"(STAGES - 2));
        __syncthreads();

        int nk = k + STAGES - 1;
        if (nk < NITER) {
            uint32_t sb = smem_base + (uint32_t)((nk % STAGES) * STAGE_F * 4);
            int koff = nk * BK;
#pragma unroll
            for (int l = 0; l < 4; l++) cp_async16(sb + xs_off[l] * 4, xg[l] + koff);
#pragma unroll
            for (int l = 0; l < 4; l++) cp_async16(sb + ws_off[l] * 4, wg[l] + koff);
        }
        asm volatile("cp.async.commit_group;\n");

        const float* Xs = smem + (k % STAGES) * STAGE_F;
        const float* Ws = Xs + X_TILE_F;

#pragma unroll
        for (int kk = 0; kk < BK; kk += 8) {
            uint32_t a[4][4], bf[8][2];
#pragma unroll
            for (int mi = 0; mi < 4; mi++) {
                int r = wm * 64 + mi * 16 + g;
                a[mi][0] = f2tf32(Xs[r * XS_STRIDE + kk + q]);
                a[mi][1] = f2tf32(Xs[(r + 8) * XS_STRIDE + kk + q]);
                a[mi][2] = f2tf32(Xs[r * XS_STRIDE + kk + q + 4]);
                a[mi][3] = f2tf32(Xs[(r + 8) * XS_STRIDE + kk + q + 4]);
            }
#pragma unroll
            for (int ni = 0; ni < 8; ni++) {
                int r = wn * 64 + ni * 8 + g;
                bf[ni][0] = f2tf32(Ws[r * XS_STRIDE + kk + q]);
                bf[ni][1] = f2tf32(Ws[r * XS_STRIDE + kk + q + 4]);
            }
#pragma unroll
            for (int mi = 0; mi < 4; mi++)
#pragma unroll
                for (int ni = 0; ni < 8; ni++)
                    mma_tf32(acc[mi][ni], a[mi], bf[ni]);
        }
    }

#pragma unroll
    for (int mi = 0; mi < 4; mi++) {
#pragma unroll
        for (int ni = 0; ni < 8; ni++) {
            int m = m0 + wm * 64 + mi * 16 + g;
            int c = h * BN + wn * 64 + ni * 8 + q * 2;
            float2 v0 = make_float2(acc[mi][ni][0], acc[mi][ni][1]);
            float2 v1 = make_float2(acc[mi][ni][2], acc[mi][ni][3]);
            *reinterpret_cast<float2*>(&g_y[(size_t)m * NTOT + c]) = v0;
            *reinterpret_cast<float2*>(&g_y[(size_t)(m + 8) * NTOT + c]) = v1;
        }
    }
}

// ---------------- Precompute k.k / k.q scalars (lag-4 layout) ----------------
__device__ __forceinline__ float wsum32(float v) {
    v += __shfl_xor_sync(0xffffffffu, v, 16);
    v += __shfl_xor_sync(0xffffffffu, v, 8);
    v += __shfl_xor_sync(0xffffffffu, v, 4);
    v += __shfl_xor_sync(0xffffffffu, v, 2);
    v += __shfl_xor_sync(0xffffffffu, v, 1);
    return v;
}
__device__ __forceinline__ float d2(float2 a, float2 b) {
    return fmaf(a.x, b.x, a.y * b.y);
}

__global__ __launch_bounds__(256, 2)
void precomp_kernel()
{
    int gw = (blockIdx.x * blockDim.x + threadIdx.x) >> 5;   // 0..32767
    int lane = threadIdx.x & 31;
    int T = gw >> 5, b = gw & 31;
    int e = lane * 2;

    const float* y = g_y;
    auto ldk = [&](int tt) -> float2 {
        return *reinterpret_cast<const float2*>(&y[(size_t)(tt * BATCH + b) * NTOT + e]);
    };
    auto ldq = [&](int tt) -> float2 {
        return *reinterpret_cast<const float2*>(&y[(size_t)(tt * BATCH + b) * NTOT + 128 + e]);
    };

    int Tp1 = T + 1 < T_STEPS ? T + 1 : T_STEPS - 1;
    int Tm1 = T - 1 >= 0 ? T - 1 : 0;
    int Tm2 = T - 2 >= 0 ? T - 2 : 0;
    int Tm3 = T - 3 >= 0 ? T - 3 : 0;

    float2 kT  = ldk(T),   qT  = ldq(T);
    float2 kp1 = ldk(Tp1), qp1 = ldq(Tp1);
    float2 km1 = ldk(Tm1), km2 = ldk(Tm2), km3 = ldk(Tm3);

    float KK2n = wsum32(d2(km1, kp1));
    float KK3n = wsum32(d2(km2, kp1));
    float KK4n = wsum32(d2(km3, kp1));
    float KK1  = wsum32(d2(km1, kT));
    float KQ2n = wsum32(d2(km1, qp1));
    float KQ3n = wsum32(d2(km2, qp1));
    float KQ4n = wsum32(d2(km3, qp1));
    float KQ1  = wsum32(d2(km1, qT));
    float KQ0  = wsum32(d2(kT,  qT));

    if (lane == 0) {
        float* p = &g_pc[(size_t)gw * 12];
        *reinterpret_cast<float4*>(p)     = make_float4(KK2n, KK3n, KK4n, KK1);
        *reinterpret_cast<float4*>(p + 4) = make_float4(KQ2n, KQ3n, KQ4n, KQ1);
        *reinterpret_cast<float4*>(p + 8) = make_float4(KQ0, 0.f, 0.f, 0.f);
    }
}

// ---------------- Scan v7: 16 lanes/row, 2 rows/warp, 1024 warps (2/SMSP) ----------------
#define SLOT_F 160           // per-t smem floats: k|q[128] v[8] ax[8] pc[12] pad
#define RINGS  32            // t-slots resident (4 groups of 8)
#define FIELDS 39            // float4 chunks per t: 32 kq + 2 v + 2 ax + 3 pc

__device__ __forceinline__ float dot4(float4 a, float4 b) {
    return fmaf(a.x, b.x, a.y * b.y) + fmaf(a.z, b.z, a.w * b.w);
}
__device__ __forceinline__ float fsig(float z) {
    return __fdividef(1.0f, 1.0f + __expf(-z));
}

__global__ __launch_bounds__(128, 2)
void scan_kernel(const float* __restrict__ S0,
                 const float* __restrict__ d_alpha,
                 const float* __restrict__ b_alpha,
                 float* __restrict__ out)
{
    __shared__ float sm[RINGS * SLOT_F];   // 20480 B

    const int tid  = threadIdx.x;
    const int b    = blockIdx.y;
    const int i0   = blockIdx.x * 8;      // 8 rows per block
    const int lane = tid & 31;
    const int w    = tid >> 5;            // 0..3
    const int rh   = lane >> 4;           // row-in-warp 0..1
    const int j16  = lane & 15;           // 16 lanes per row
    const int i    = i0 + w * 2 + rh;     // global row
    const int c0   = j16 * 4;             // column base (4 elems/lane)
    const int il   = i - i0;              // 0..7

    // ---- 3 prefetch descriptors/thread (39 float4 per t, 312 per group of 8) ----
    const float* dsrc[3];
    int dstride[3], ddst[3], dtl[3];
    bool dvalid[3];
#pragma unroll
    for (int l = 0; l < 3; l++) {
        int c = tid + l * 128;
        dvalid[l] = (c < 8 * FIELDS);
        int tl = c / FIELDS, f = c - tl * FIELDS;
        dtl[l] = tl;
        int srcoff, dstf;
        if (f < 32)      { srcoff = (f < 16 ? f * 4 : 128 + (f - 16) * 4); dstf = f * 4; }
        else if (f < 34) { srcoff = 64  + i0 + (f - 32) * 4; dstf = 128 + (f - 32) * 4; }
        else if (f < 36) { srcoff = 192 + i0 + (f - 34) * 4; dstf = 136 + (f - 34) * 4; }
        else             { srcoff = (f - 36) * 4;            dstf = 144 + (f - 36) * 4; }
        if (f < 36) { dsrc[l] = g_y  + (size_t)b * NTOT + srcoff; dstride[l] = BATCH * NTOT; }
        else        { dsrc[l] = g_pc + (size_t)b * 12   + srcoff; dstride[l] = BATCH * 12;  }
        ddst[l] = tl * SLOT_F + dstf;
    }
    uint32_t smb = (uint32_t)__cvta_generic_to_shared(sm);

    auto issue_group = [&](int gidx) {
#pragma unroll
        for (int l = 0; l < 3; l++) {
            if (dvalid[l]) {
                int t  = gidx * 8 + dtl[l];
                int tc = t < T_STEPS ? t : T_STEPS - 1;
                cp_async16(smb + (uint32_t)(((gidx & 3) * 8 * SLOT_F + ddst[l]) * 4),
                           dsrc[l] + (size_t)tc * dstride[l]);
            }
        }
        asm volatile("cp.async.commit_group;\n");
    };

    issue_group(0);
    issue_group(1);
    issue_group(2);

    float4 s0v = *reinterpret_cast<const float4*>(&S0[((size_t)b * NH + i) * NH + c0]);
    const float da  = d_alpha[i];
    const float bap = b_alpha[i];

    asm volatile("cp.async.wait_group 2;\n");
    __syncthreads();

    auto K4 = [&](int t, int c) -> float4 {
        return *reinterpret_cast<const float4*>(&sm[(t & (RINGS - 1)) * SLOT_F + c]);
    };
    auto Q4 = [&](int t, int c) -> float4 {
        return *reinterpret_cast<const float4*>(&sm[(t & (RINGS - 1)) * SLOT_F + 64 + c]);
    };

    // k(t) register ring (8 slots)
    float4 kr[8];
#pragma unroll
    for (int j = 0; j < 4; j++) kr[j] = K4(j, c0);

    // 16-lane reductions: levels are xor 8, 4, 2, 1
    auto full16 = [&](float v) -> float {
        v += __shfl_xor_sync(0xffffffffu, v, 8);
        v += __shfl_xor_sync(0xffffffffu, v, 4);
        v += __shfl_xor_sync(0xffffffffu, v, 2);
        v += __shfl_xor_sync(0xffffffffu, v, 1);
        return v;
    };
    auto lvl2of16 = [&](float v) -> float {   // first two levels
        v += __shfl_xor_sync(0xffffffffu, v, 8);
        v += __shfl_xor_sync(0xffffffffu, v, 4);
        return v;
    };
    auto lvl3of16 = [&](float v) -> float {   // first three levels
        v += __shfl_xor_sync(0xffffffffu, v, 8);
        v += __shfl_xor_sync(0xffffffffu, v, 4);
        v += __shfl_xor_sync(0xffffffffu, v, 2);
        return v;
    };

    // Prologue (s(-1)=S0; alpha(<0)=1, c(<0)=0):
    //  KG = full s0.k(0), KP = full s0.k(1), KC = 3-level s0.k(2), KB = 2-level s0.k(3)
    float KG = full16(dot4(s0v, kr[0]));
    float KP = full16(dot4(s0v, kr[1]));
    float KC = lvl3of16(dot4(s0v, kr[2]));
    float KB = lvl2of16(dot4(s0v, kr[3]));
    float QG = full16(dot4(s0v, Q4(0, c0)));
    float QP = full16(dot4(s0v, Q4(1, c0)));
    float QC = lvl3of16(dot4(s0v, Q4(2, c0)));
    float QB = lvl2of16(dot4(s0v, Q4(3, c0)));

    float a1 = 1.0f, a2 = 1.0f, a3 = 1.0f;
    float c1 = 0.0f, c2 = 0.0f, c3 = 0.0f;

    float* __restrict__ out_bi = out + b * NH + i;

    for (int m = 0; m < T_STEPS / 8; m++) {
        asm volatile("cp.async.wait_group 1;\n");
        __syncthreads();

#pragma unroll
        for (int u = 0; u < 8; u++) {
            const int t = m * 8 + u;
            const float* sp = &sm[(t & (RINGS - 1)) * SLOT_F];

            float4 kp4 = K4(t + 4, c0);                        // k(t+4)
            float4 qp4 = Q4(t + 4, c0);                        // q(t+4)
            float  vt  = sp[128 + il];
            float  axb = sp[136 + il] + bap;
            float4 pA  = *reinterpret_cast<const float4*>(&sp[144]);  // KK2',KK3',KK4',KK1
            float4 pB  = *reinterpret_cast<const float4*>(&sp[148]);  // KQ2',KQ3',KQ4',KQ1
            float  kq0 = sp[152];                                      // KQ0(t)

            // pipelined butterfly stages
            float KBn = lvl2of16(dot4(s0v, kp4));              // target t+4 (lvl 1+2)
            float KCn = KB + __shfl_xor_sync(0xffffffffu, KB, 2);   // target t+3 (lvl 3)
            float KPn = KC + __shfl_xor_sync(0xffffffffu, KC, 1);   // target t+2 (lvl 4, full)
            float QBn = lvl2of16(dot4(s0v, qp4));
            float QCn = QB + __shfl_xor_sync(0xffffffffu, QB, 2);
            float QPn = QC + __shfl_xor_sync(0xffffffffu, QC, 1);

            // recurrence critical path: final correction for target t
            float rk    = fmaf(a1, KG, c1 * pA.w);
            float z     = fmaf(da, rk, axb);
            float alpha = fsig(z);
            float cc    = (1.0f - alpha) * vt;

            // output h(t)
            float N3 = fmaf(a1, QG, c1 * pB.w);
            float h  = fmaf(alpha, N3, cc * kq0);

            // batched corrections for target t+1
            float gk  = fmaf(a3, KP, c3 * pA.z);
            gk        = fmaf(a2, gk, c2 * pA.y);
            float KGn = fmaf(a1, gk, c1 * pA.x);
            float gq  = fmaf(a3, QP, c3 * pB.z);
            gq        = fmaf(a2, gq, c2 * pB.y);
            float QGn = fmaf(a1, gq, c1 * pB.x);

            // state update with k(t) from register ring
            float4 kc = kr[u & 7];
            s0v.x = fmaf(alpha, s0v.x, cc * kc.x);
            s0v.y = fmaf(alpha, s0v.y, cc * kc.y);
            s0v.z = fmaf(alpha, s0v.z, cc * kc.z);
            s0v.w = fmaf(alpha, s0v.w, cc * kc.w);
            kr[(u + 4) & 7] = kp4;

            // rotate pipelines
            KB = KBn; KC = KCn; KP = KPn; KG = KGn;
            QB = QBn; QC = QCn; QP = QPn; QG = QGn;
            a3 = a2; a2 = a1; a1 = alpha;
            c3 = c2; c2 = c1; c1 = cc;

            if (j16 == 0) {
                float sg = fsig(h);
                out_bi[(size_t)t * (BATCH * NH)] = h * h * sg;
            }
        }

        issue_group(m + 3);
    }

    float* sf = out + (size_t)T_STEPS * BATCH * NH;
    *reinterpret_cast<float4*>(&sf[((size_t)b * NH + i) * NH + c0]) = s0v;
}

extern "C" void kernel_launch(void* const* d_in, const int* in_sizes, int n_in,
                              void* d_out, int out_size)
{
    const float* x  = (const float*)d_in[0];
    const float* S0 = (const float*)d_in[1];
    const float* Wk = (const float*)d_in[2];
    const float* Wv = (const float*)d_in[3];
    const float* Wq = (const float*)d_in[4];
    const float* Wa = (const float*)d_in[5];
    const float* da = (const float*)d_in[6];
    const float* ba = (const float*)d_in[7];
    float* out = (float*)d_out;
    (void)out_size;

    cudaFuncSetAttribute(proj_gemm, cudaFuncAttributeMaxDynamicSharedMemorySize, SMEM_BYTES);

    proj_gemm<<<dim3(M_TOTAL / BM, 2), 128, SMEM_BYTES>>>(x, Wk, Wv, Wq, Wa);
    precomp_kernel<<<M_TOTAL / 8, 256>>>();
    scan_kernel<<<dim3(8, BATCH), 128>>>(S0, da, ba, out);
}

// round 8
// speedup vs baseline: 1.0010x; 1.0010x over previous
#include <cuda_runtime.h>
#include <cstdint>

// Problem constants
#define T_STEPS 1024
#define BATCH   32
#define DIM     1024
#define NH      64
#define NTOT    256                 // 4 * NH (k | v | q | ax)
#define M_TOTAL (T_STEPS * BATCH)   // 32768

// Scratch: projections Y[m][256], m = t*BATCH+b  (32 MB)
__device__ float g_y[(size_t)M_TOTAL * NTOT];
// Precomputed per-(t,b) dot scalars, 12 floats per slot T:
//  [0..3]: KK2(T+1), KK3(T+1), KK4(T+1), KK1(T)
//  [4..7]: KQ2(T+1), KQ3(T+1), KQ4(T+1), KQ1(T)
//  [8]   : KQ0(T)
__device__ float g_pc[(size_t)M_TOTAL * 12];

// ---------------- GEMM (tf32 mma.sync) — R3/R6 version (best measured: 153us) ----------------
#define BM 128
#define BK 16
#define STAGES 3
#define XS_STRIDE 20
#define X_TILE_F (BM * XS_STRIDE)
#define W_TILE_F (NTOT * XS_STRIDE)
#define STAGE_F  (X_TILE_F + W_TILE_F)
#define SMEM_BYTES (STAGES * STAGE_F * 4)

__device__ __forceinline__ void cp_async16(uint32_t saddr, const void* gptr) {
    asm volatile("cp.async.cg.shared.global [%0], [%1], 16;\n" :: "r"(saddr), "l"(gptr));
}
__device__ __forceinline__ uint32_t f2tf32(float f) {
    uint32_t r;
    asm("cvt.rna.tf32.f32 %0, %1;" : "=r"(r) : "f"(f));
    return r;
}
__device__ __forceinline__ void mma_tf32(float* c, const uint32_t* a, const uint32_t* b) {
    asm volatile(
        "mma.sync.aligned.m16n8k8.row.col.f32.tf32.tf32.f32 "
        "{%0,%1,%2,%3}, {%4,%5,%6,%7}, {%8,%9}, {%0,%1,%2,%3};"
        : "+f"(c[0]), "+f"(c[1]), "+f"(c[2]), "+f"(c[3])
        : "r"(a[0]), "r"(a[1]), "r"(a[2]), "r"(a[3]), "r"(b[0]), "r"(b[1]));
}

__global__ __launch_bounds__(256, 1)
void proj_gemm(const float* __restrict__ X,
               const float* __restrict__ Wk, const float* __restrict__ Wv,
               const float* __restrict__ Wq, const float* __restrict__ Wa)
{
    extern __shared__ float smem[];
    const int tid = threadIdx.x;
    const int m0  = blockIdx.x * BM;

    const float* wptr[4] = {Wk, Wv, Wq, Wa};

    const float* xg[2];
    uint32_t xs_off[2];
#pragma unroll
    for (int l = 0; l < 2; l++) {
        int f = tid + l * 256;
        int row = f >> 2, c4 = f & 3;
        xg[l] = X + (size_t)(m0 + row) * DIM + c4 * 4;
        xs_off[l] = (uint32_t)(row * XS_STRIDE + c4 * 4);
    }
    const float* wg[4];
    uint32_t ws_off[4];
#pragma unroll
    for (int l = 0; l < 4; l++) {
        int f = tid + l * 256;
        int row = f >> 2, c4 = f & 3;
        wg[l] = wptr[row >> 6] + (size_t)(row & 63) * DIM + c4 * 4;
        ws_off[l] = (uint32_t)(X_TILE_F + row * XS_STRIDE + c4 * 4);
    }
    uint32_t smem_base = (uint32_t)__cvta_generic_to_shared(smem);

    const int lane = tid & 31;
    const int w    = tid >> 5;
    const int g    = lane >> 2;
    const int q    = lane & 3;
    const int wm   = w >> 2;
    const int wn   = w & 3;

    float acc[4][8][4];
#pragma unroll
    for (int mi = 0; mi < 4; mi++)
#pragma unroll
        for (int ni = 0; ni < 8; ni++)
#pragma unroll
            for (int r = 0; r < 4; r++) acc[mi][ni][r] = 0.0f;

    const int NITER = DIM / BK;

#pragma unroll
    for (int s = 0; s < STAGES - 1; s++) {
        uint32_t sb = smem_base + (uint32_t)((s % STAGES) * STAGE_F * 4);
        int koff = s * BK;
#pragma unroll
        for (int l = 0; l < 2; l++) cp_async16(sb + xs_off[l] * 4, xg[l] + koff);
#pragma unroll
        for (int l = 0; l < 4; l++) cp_async16(sb + ws_off[l] * 4, wg[l] + koff);
        asm volatile("cp.async.commit_group;\n");
    }

    for (int k = 0; k < NITER; k++) {
        asm volatile("cp.async.wait_group %0;\n" :: "n"(STAGES - 2));
        __syncthreads();

        int nk = k + STAGES - 1;
        if (nk < NITER) {
            uint32_t sb = smem_base + (uint32_t)((nk % STAGES) * STAGE_F * 4);
            int koff = nk * BK;
#pragma unroll
            for (int l = 0; l < 2; l++) cp_async16(sb + xs_off[l] * 4, xg[l] + koff);
#pragma unroll
            for (int l = 0; l < 4; l++) cp_async16(sb + ws_off[l] * 4, wg[l] + koff);
        }
        asm volatile("cp.async.commit_group;\n");

        const float* Xs = smem + (k % STAGES) * STAGE_F;
        const float* Ws = Xs + X_TILE_F;

#pragma unroll
        for (int kk = 0; kk < BK; kk += 8) {
            uint32_t a[4][4], bf[8][2];
#pragma unroll
            for (int mi = 0; mi < 4; mi++) {
                int r = wm * 64 + mi * 16 + g;
                a[mi][0] = f2tf32(Xs[r * XS_STRIDE + kk + q]);
                a[mi][1] = f2tf32(Xs[(r + 8) * XS_STRIDE + kk + q]);
                a[mi][2] = f2tf32(Xs[r * XS_STRIDE + kk + q + 4]);
                a[mi][3] = f2tf32(Xs[(r + 8) * XS_STRIDE + kk + q + 4]);
            }
#pragma unroll
            for (int ni = 0; ni < 8; ni++) {
                int r = wn * 64 + ni * 8 + g;
                bf[ni][0] = f2tf32(Ws[r * XS_STRIDE + kk + q]);
                bf[ni][1] = f2tf32(Ws[r * XS_STRIDE + kk + q + 4]);
            }
#pragma unroll
            for (int mi = 0; mi < 4; mi++)
#pragma unroll
                for (int ni = 0; ni < 8; ni++)
                    mma_tf32(acc[mi][ni], a[mi], bf[ni]);
        }
    }

#pragma unroll
    for (int mi = 0; mi < 4; mi++) {
#pragma unroll
        for (int ni = 0; ni < 8; ni++) {
            int m = m0 + wm * 64 + mi * 16 + g;
            int c = wn * 64 + ni * 8 + q * 2;
            float2 v0 = make_float2(acc[mi][ni][0], acc[mi][ni][1]);
            float2 v1 = make_float2(acc[mi][ni][2], acc[mi][ni][3]);
            *reinterpret_cast<float2*>(&g_y[(size_t)m * NTOT + c]) = v0;
            *reinterpret_cast<float2*>(&g_y[(size_t)(m + 8) * NTOT + c]) = v1;
        }
    }
}

// ---------------- Precompute k.k / k.q scalars (lag-4 layout) ----------------
__device__ __forceinline__ float wsum32(float v) {
    v += __shfl_xor_sync(0xffffffffu, v, 16);
    v += __shfl_xor_sync(0xffffffffu, v, 8);
    v += __shfl_xor_sync(0xffffffffu, v, 4);
    v += __shfl_xor_sync(0xffffffffu, v, 2);
    v += __shfl_xor_sync(0xffffffffu, v, 1);
    return v;
}
__device__ __forceinline__ float d2(float2 a, float2 b) {
    return fmaf(a.x, b.x, a.y * b.y);
}

__global__ __launch_bounds__(256, 2)
void precomp_kernel()
{
    int gw = (blockIdx.x * blockDim.x + threadIdx.x) >> 5;   // 0..32767
    int lane = threadIdx.x & 31;
    int T = gw >> 5, b = gw & 31;
    int e = lane * 2;

    const float* y = g_y;
    auto ldk = [&](int tt) -> float2 {
        return *reinterpret_cast<const float2*>(&y[(size_t)(tt * BATCH + b) * NTOT + e]);
    };
    auto ldq = [&](int tt) -> float2 {
        return *reinterpret_cast<const float2*>(&y[(size_t)(tt * BATCH + b) * NTOT + 128 + e]);
    };

    int Tp1 = T + 1 < T_STEPS ? T + 1 : T_STEPS - 1;
    int Tm1 = T - 1 >= 0 ? T - 1 : 0;
    int Tm2 = T - 2 >= 0 ? T - 2 : 0;
    int Tm3 = T - 3 >= 0 ? T - 3 : 0;

    float2 kT  = ldk(T),   qT  = ldq(T);
    float2 kp1 = ldk(Tp1), qp1 = ldq(Tp1);
    float2 km1 = ldk(Tm1), km2 = ldk(Tm2), km3 = ldk(Tm3);

    float KK2n = wsum32(d2(km1, kp1));
    float KK3n = wsum32(d2(km2, kp1));
    float KK4n = wsum32(d2(km3, kp1));
    float KK1  = wsum32(d2(km1, kT));
    float KQ2n = wsum32(d2(km1, qp1));
    float KQ3n = wsum32(d2(km2, qp1));
    float KQ4n = wsum32(d2(km3, qp1));
    float KQ1  = wsum32(d2(km1, qT));
    float KQ0  = wsum32(d2(kT,  qT));

    if (lane == 0) {
        float* p = &g_pc[(size_t)gw * 12];
        *reinterpret_cast<float4*>(p)     = make_float4(KK2n, KK3n, KK4n, KK1);
        *reinterpret_cast<float4*>(p + 4) = make_float4(KQ2n, KQ3n, KQ4n, KQ1);
        *reinterpret_cast<float4*>(p + 8) = make_float4(KQ0, 0.f, 0.f, 0.f);
    }
}

// ---------------- Scan v8: deferred state update — sigmoid latency shadowed ----------------
#define SLOT_F 160           // per-t smem floats: k|q[128] v[8] ax[8] pc[12] pad
#define RINGS  32
#define FIELDS 39            // float4 chunks per t

__device__ __forceinline__ float dot4(float4 a, float4 b) {
    return fmaf(a.x, b.x, a.y * b.y) + fmaf(a.z, b.z, a.w * b.w);
}

__global__ __launch_bounds__(128, 2)
void scan_kernel(const float* __restrict__ S0,
                 const float* __restrict__ d_alpha,
                 const float* __restrict__ b_alpha,
                 float* __restrict__ out)
{
    __shared__ float sm[RINGS * SLOT_F];   // 20480 B

    const int tid  = threadIdx.x;
    const int b    = blockIdx.y;
    const int i0   = blockIdx.x * 8;
    const int lane = tid & 31;
    const int w    = tid >> 5;
    const int rh   = lane >> 4;
    const int j16  = lane & 15;
    const int i    = i0 + w * 2 + rh;
    const int c0   = j16 * 4;
    const int il   = i - i0;

    const float* dsrc[3];
    int dstride[3], ddst[3], dtl[3];
    bool dvalid[3];
#pragma unroll
    for (int l = 0; l < 3; l++) {
        int c = tid + l * 128;
        dvalid[l] = (c < 8 * FIELDS);
        int tl = c / FIELDS, f = c - tl * FIELDS;
        dtl[l] = tl;
        int srcoff, dstf;
        if (f < 32)      { srcoff = (f < 16 ? f * 4 : 128 + (f - 16) * 4); dstf = f * 4; }
        else if (f < 34) { srcoff = 64  + i0 + (f - 32) * 4; dstf = 128 + (f - 32) * 4; }
        else if (f < 36) { srcoff = 192 + i0 + (f - 34) * 4; dstf = 136 + (f - 34) * 4; }
        else             { srcoff = (f - 36) * 4;            dstf = 144 + (f - 36) * 4; }
        if (f < 36) { dsrc[l] = g_y  + (size_t)b * NTOT + srcoff; dstride[l] = BATCH * NTOT; }
        else        { dsrc[l] = g_pc + (size_t)b * 12   + srcoff; dstride[l] = BATCH * 12;  }
        ddst[l] = tl * SLOT_F + dstf;
    }
    uint32_t smb = (uint32_t)__cvta_generic_to_shared(sm);

    auto issue_group = [&](int gidx) {
#pragma unroll
        for (int l = 0; l < 3; l++) {
            if (dvalid[l]) {
                int t  = gidx * 8 + dtl[l];
                int tc = t < T_STEPS ? t : T_STEPS - 1;
                cp_async16(smb + (uint32_t)(((gidx & 3) * 8 * SLOT_F + ddst[l]) * 4),
                           dsrc[l] + (size_t)tc * dstride[l]);
            }
        }
        asm volatile("cp.async.commit_group;\n");
    };

    issue_group(0);
    issue_group(1);
    issue_group(2);

    float4 s0v = *reinterpret_cast<const float4*>(&S0[((size_t)b * NH + i) * NH + c0]);
    const float da  = d_alpha[i];
    const float bap = b_alpha[i];

    asm volatile("cp.async.wait_group 2;\n");
    __syncthreads();

    auto K4 = [&](int t, int c) -> float4 {
        return *reinterpret_cast<const float4*>(&sm[(t & (RINGS - 1)) * SLOT_F + c]);
    };
    auto Q4 = [&](int t, int c) -> float4 {
        return *reinterpret_cast<const float4*>(&sm[(t & (RINGS - 1)) * SLOT_F + 64 + c]);
    };

    float4 kr[8];
#pragma unroll
    for (int j = 0; j < 4; j++) kr[j] = K4(j, c0);

    auto full16 = [&](float v) -> float {
        v += __shfl_xor_sync(0xffffffffu, v, 8);
        v += __shfl_xor_sync(0xffffffffu, v, 4);
        v += __shfl_xor_sync(0xffffffffu, v, 2);
        v += __shfl_xor_sync(0xffffffffu, v, 1);
        return v;
    };
    auto lvl2of16 = [&](float v) -> float {
        v += __shfl_xor_sync(0xffffffffu, v, 8);
        v += __shfl_xor_sync(0xffffffffu, v, 4);
        return v;
    };
    auto lvl3of16 = [&](float v) -> float {
        v += __shfl_xor_sync(0xffffffffu, v, 8);
        v += __shfl_xor_sync(0xffffffffu, v, 4);
        v += __shfl_xor_sync(0xffffffffu, v, 2);
        return v;
    };

    // Prologue (s(-1)=S0; alpha(<0)=1, c(<0)=0)
    float KG = full16(dot4(s0v, kr[0]));
    float KP = full16(dot4(s0v, kr[1]));
    float KC = lvl3of16(dot4(s0v, kr[2]));
    float KB = lvl2of16(dot4(s0v, kr[3]));
    float QG = full16(dot4(s0v, Q4(0, c0)));
    float QP = full16(dot4(s0v, Q4(1, c0)));
    float QC = lvl3of16(dot4(s0v, Q4(2, c0)));
    float QB = lvl2of16(dot4(s0v, Q4(3, c0)));

    // Deferred-update carries: aP = alpha(t-1), cP = cc(t-1), kP = k(t-1)
    float aP = 1.0f, a2 = 1.0f, a3 = 1.0f;
    float cP = 0.0f, c2 = 0.0f, c3 = 0.0f;
    float4 kP = make_float4(0.f, 0.f, 0.f, 0.f);

    float* __restrict__ out_bi = out + b * NH + i;

    for (int m = 0; m < T_STEPS / 8; m++) {
        asm volatile("cp.async.wait_group 1;\n");
        __syncthreads();

#pragma unroll
        for (int u = 0; u < 8; u++) {
            const int t = m * 8 + u;
            const float* sp = &sm[(t & (RINGS - 1)) * SLOT_F];

            // loads
            float4 kp4 = K4(t + 4, c0);
            float4 qp4 = Q4(t + 4, c0);
            float  vt  = sp[128 + il];
            float  axb = sp[136 + il] + bap;
            float4 pA  = *reinterpret_cast<const float4*>(&sp[144]);  // KK2',KK3',KK4',KK1
            float4 pB  = *reinterpret_cast<const float4*>(&sp[148]);  // KQ2',KQ3',KQ4',KQ1
            float  kq0 = sp[152];

            // (1) z(t) from carried values — then ISSUE the sigmoid MUFU chain.
            float rk = fmaf(aP, KG, cP * pA.w);
            float z  = fmaf(da, rk, axb);
            float en = __expf(-z);               // MUFU.EX2 chain in flight

            // (2) deferred state update: s -> s(t-1)   (alpha(t)-independent)
            s0v.x = fmaf(aP, s0v.x, cP * kP.x);
            s0v.y = fmaf(aP, s0v.y, cP * kP.y);
            s0v.z = fmaf(aP, s0v.z, cP * kP.z);
            s0v.w = fmaf(aP, s0v.w, cP * kP.w);

            // (3) dots + pipelined butterfly stages on s(t-1)  (alpha(t)-independent)
            float KBn = lvl2of16(dot4(s0v, kp4));                    // target t+4
            float KCn = KB + __shfl_xor_sync(0xffffffffu, KB, 2);    // target t+3
            float KPn = KC + __shfl_xor_sync(0xffffffffu, KC, 1);    // target t+2 (full)
            float QBn = lvl2of16(dot4(s0v, qp4));
            float QCn = QB + __shfl_xor_sync(0xffffffffu, QB, 2);
            float QPn = QC + __shfl_xor_sync(0xffffffffu, QC, 1);

            // (4) correction chains with older alphas (alpha(t)-independent)
            float gk  = fmaf(a3, KP, c3 * pA.z);
            gk        = fmaf(a2, gk, c2 * pA.y);
            float gkF = fmaf(aP, gk, cP * pA.x);   // KG(t+1)
            float gq  = fmaf(a3, QP, c3 * pB.z);
            gq        = fmaf(a2, gq, c2 * pB.y);
            float gqF = fmaf(aP, gq, cP * pB.x);   // QG(t+1)
            float N3  = fmaf(aP, QG, cP * pB.w);

            // (5) consume alpha(t) — MUFU latency now shadowed by (2)-(4)
            float alpha = __fdividef(1.0f, 1.0f + en);
            float cc    = (1.0f - alpha) * vt;
            float h     = fmaf(alpha, N3, cc * kq0);

            // (6) rotate
            KB = KBn; KC = KCn; KP = KPn; KG = gkF;
            QB = QBn; QC = QCn; QP = QPn; QG = gqF;
            a3 = a2; a2 = aP; aP = alpha;
            c3 = c2; c2 = cP; cP = cc;
            kP = kr[u & 7];
            kr[(u + 4) & 7] = kp4;

            if (j16 == 0) {
                float sg = __fdividef(1.0f, 1.0f + __expf(-h));
                out_bi[(size_t)t * (BATCH * NH)] = h * h * sg;
            }
        }

        issue_group(m + 3);
    }

    // Epilogue: finish last state update -> s(T-1)
    s0v.x = fmaf(aP, s0v.x, cP * kP.x);
    s0v.y = fmaf(aP, s0v.y, cP * kP.y);
    s0v.z = fmaf(aP, s0v.z, cP * kP.z);
    s0v.w = fmaf(aP, s0v.w, cP * kP.w);

    float* sf = out + (size_t)T_STEPS * BATCH * NH;
    *reinterpret_cast<float4*>(&sf[((size_t)b * NH + i) * NH + c0]) = s0v;
}

extern "C" void kernel_launch(void* const* d_in, const int* in_sizes, int n_in,
                              void* d_out, int out_size)
{
    const float* x  = (const float*)d_in[0];
    const float* S0 = (const float*)d_in[1];
    const float* Wk = (const float*)d_in[2];
    const float* Wv = (const float*)d_in[3];
    const float* Wq = (const float*)d_in[4];
    const float* Wa = (const float*)d_in[5];
    const float* da = (const float*)d_in[6];
    const float* ba = (const float*)d_in[7];
    float* out = (float*)d_out;
    (void)out_size;

    cudaFuncSetAttribute(proj_gemm, cudaFuncAttributeMaxDynamicSharedMemorySize, SMEM_BYTES);

    proj_gemm<<<M_TOTAL / BM, 256, SMEM_BYTES>>>(x, Wk, Wv, Wq, Wa);
    precomp_kernel<<<M_TOTAL / 8, 256>>>();
    scan_kernel<<<dim3(8, BATCH), 128>>>(S0, da, ba, out);
}

// round 12
// speedup vs baseline: 1.2651x; 1.2639x over previous
#include <cuda_runtime.h>
#include <cuda_fp16.h>
#include <cstdint>

// Problem constants
#define T_STEPS 1024
#define BATCH   32
#define DIM     1024
#define NH      64
#define NTOT    256                 // 4 * NH (k | v | q | ax)
#define M_TOTAL (T_STEPS * BATCH)   // 32768

// Scratch buffers
__device__ float g_y[(size_t)M_TOTAL * NTOT];          // projections (fp32 out)
__device__ float g_pc[(size_t)M_TOTAL * 12];           // precomputed scalars
__device__ half  g_xh[(size_t)M_TOTAL * DIM];          // X in fp16
__device__ half  g_wh[(size_t)NTOT * DIM];             // stacked W in fp16

// ---------------- fp32 -> fp16 conversion ----------------
__global__ __launch_bounds__(256, 4)
void conv_x(const float4* __restrict__ X4)
{
    const size_t n4 = (size_t)M_TOTAL * DIM / 4;
    for (size_t i = (size_t)blockIdx.x * blockDim.x + threadIdx.x; i < n4;
         i += (size_t)gridDim.x * blockDim.x) {
        float4 v = X4[i];
        half2 h0 = __floats2half2_rn(v.x, v.y);
        half2 h1 = __floats2half2_rn(v.z, v.w);
        uint2 o;
        o.x = *reinterpret_cast<uint32_t*>(&h0);
        o.y = *reinterpret_cast<uint32_t*>(&h1);
        *reinterpret_cast<uint2*>(&g_xh[i * 4]) = o;
    }
}

__global__ __launch_bounds__(256, 4)
void conv_w(const float* __restrict__ Wk, const float* __restrict__ Wv,
            const float* __restrict__ Wq, const float* __restrict__ Wa)
{
    int i = blockIdx.x * blockDim.x + threadIdx.x;   // 0 .. 256*1024-1
    if (i < NTOT * DIM) {
        int row = i >> 10, col = i & 1023;
        const float* wptr[4] = {Wk, Wv, Wq, Wa};
        g_wh[i] = __float2half_rn(wptr[row >> 6][(size_t)(row & 63) * DIM + col]);
    }
}

// ---------------- GEMM (fp16 mma + ldmatrix) ----------------
// Block tile 128(M) x 256(N) x 64(K-halves). 8 warps: wm in {0,1} (64 rows), wn in {0..3} (64 cols).
// smem rows: 128 bytes (64 halves), 8x 16B chunks, swizzle chunk' = chunk ^ (row & 7).
#define XT_B  (128 * 128)           // X tile bytes
#define WT_B  (256 * 128)           // W tile bytes
#define STG_B (XT_B + WT_B)         // 49152
#define GSTAGES 3
#define GSMEM (GSTAGES * STG_B)     // 147456

__device__ __forceinline__ void cp_async16(uint32_t saddr, const void* gptr) {
    asm volatile("cp.async.cg.shared.global [%0], [%1], 16;\n" :: "r"(saddr), "l"(gptr));
}
__device__ __forceinline__ void ldsm4(uint32_t& r0, uint32_t& r1, uint32_t& r2, uint32_t& r3,
                                      uint32_t addr) {
    asm volatile("ldmatrix.sync.aligned.m8n8.x4.shared.b16 {%0,%1,%2,%3}, [%4];"
                 : "=r"(r0), "=r"(r1), "=r"(r2), "=r"(r3) : "r"(addr));
}
__device__ __forceinline__ void mma_f16(float* c, const uint32_t* a, uint32_t b0, uint32_t b1) {
    asm volatile(
        "mma.sync.aligned.m16n8k16.row.col.f32.f16.f16.f32 "
        "{%0,%1,%2,%3}, {%4,%5,%6,%7}, {%8,%9}, {%0,%1,%2,%3};"
        : "+f"(c[0]), "+f"(c[1]), "+f"(c[2]), "+f"(c[3])
        : "r"(a[0]), "r"(a[1]), "r"(a[2]), "r"(a[3]), "r"(b0), "r"(b1));
}

__global__ __launch_bounds__(256, 1)
void proj_gemm()
{
    extern __shared__ char smem[];
    const int tid = threadIdx.x;
    const int m0  = blockIdx.x * 128;

    // cp.async descriptors: 3072 16B chunks/stage (X 1024 + W 2048), 12/thread.
    const half* csrc[12];
    uint32_t cdst[12];
#pragma unroll
    for (int j = 0; j < 12; j++) {
        int cid = tid + j * 256;
        if (cid < 1024) {                 // X chunk
            int r = cid >> 3, c = cid & 7;
            csrc[j] = g_xh + (size_t)(m0 + r) * DIM + c * 8;
            cdst[j] = (uint32_t)(r * 128 + ((c ^ (r & 7)) << 4));
        } else {                          // W chunk
            int wi = cid - 1024;
            int r = wi >> 3, c = wi & 7;
            csrc[j] = g_wh + (size_t)r * DIM + c * 8;
            cdst[j] = (uint32_t)(XT_B + r * 128 + ((c ^ (r & 7)) << 4));
        }
    }
    uint32_t smem_base = (uint32_t)__cvta_generic_to_shared(smem);

    const int lane = tid & 31;
    const int w    = tid >> 5;
    const int wm   = w >> 2;     // 0..1
    const int wn   = w & 3;      // 0..3
    const int g    = lane >> 2;
    const int q    = lane & 3;

    float acc[4][8][4];
#pragma unroll
    for (int mi = 0; mi < 4; mi++)
#pragma unroll
        for (int ni = 0; ni < 8; ni++)
#pragma unroll
            for (int r = 0; r < 4; r++) acc[mi][ni][r] = 0.0f;

    const int NITER = DIM / 64;   // 16

#pragma unroll
    for (int s = 0; s < GSTAGES - 1; s++) {
        uint32_t sb = smem_base + (uint32_t)(s * STG_B);
        int koff = s * 64;
#pragma unroll
        for (int j = 0; j < 12; j++) cp_async16(sb + cdst[j], csrc[j] + koff);
        asm volatile("cp.async.commit_group;\n");
    }

    // Per-lane ldmatrix row bases (fixed across iters)
    const int arow_l = (lane & 15);                       // A: rows 0..15 within mi tile
    const int aksel  = (lane >> 4);                       // A: +chunk for k8-15
    const int brow_l = (lane & 7) + ((lane >> 4) << 3);   // B: n rows 0..15 within nb tile
    const int bksel  = (lane >> 3) & 1;                   // B: +chunk for k8-15

    for (int k = 0; k < NITER; k++) {
        asm volatile("cp.async.wait_group %0;\n" :: "n"(GSTAGES - 2));
        __syncthreads();

        int nk = k + GSTAGES - 1;
        if (nk < NITER) {
            uint32_t sb = smem_base + (uint32_t)((nk % GSTAGES) * STG_B);
            int koff = nk * 64;
#pragma unroll
            for (int j = 0; j < 12; j++) cp_async16(sb + cdst[j], csrc[j] + koff);
        }
        asm volatile("cp.async.commit_group;\n");

        uint32_t XsB = smem_base + (uint32_t)((k % GSTAGES) * STG_B);
        uint32_t WsB = XsB + XT_B;

#pragma unroll
        for (int kk = 0; kk < 4; kk++) {     // 4 x k16 per 64-K stage
            uint32_t a[4][4], bfr[4][4];
            int akc = kk * 2 + aksel;
            int bkc = kk * 2 + bksel;
#pragma unroll
            for (int mi = 0; mi < 4; mi++) {
                int row = wm * 64 + mi * 16 + arow_l;
                uint32_t addr = XsB + (uint32_t)(row * 128 + ((akc ^ (row & 7)) << 4));
                ldsm4(a[mi][0], a[mi][1], a[mi][2], a[mi][3], addr);
            }
#pragma unroll
            for (int nb = 0; nb < 4; nb++) {
                int nrow = wn * 64 + nb * 16 + brow_l;
                uint32_t addr = WsB + (uint32_t)(nrow * 128 + ((bkc ^ (nrow & 7)) << 4));
                ldsm4(bfr[nb][0], bfr[nb][1], bfr[nb][2], bfr[nb][3], addr);
            }
#pragma unroll
            for (int mi = 0; mi < 4; mi++)
#pragma unroll
                for (int nb = 0; nb < 4; nb++) {
                    mma_f16(acc[mi][nb * 2],     a[mi], bfr[nb][0], bfr[nb][1]);
                    mma_f16(acc[mi][nb * 2 + 1], a[mi], bfr[nb][2], bfr[nb][3]);
                }
        }
    }

    // Epilogue
#pragma unroll
    for (int mi = 0; mi < 4; mi++) {
#pragma unroll
        for (int ni = 0; ni < 8; ni++) {
            int m = m0 + wm * 64 + mi * 16 + g;
            int c = wn * 64 + ni * 8 + q * 2;
            float2 v0 = make_float2(acc[mi][ni][0], acc[mi][ni][1]);
            float2 v1 = make_float2(acc[mi][ni][2], acc[mi][ni][3]);
            *reinterpret_cast<float2*>(&g_y[(size_t)m * NTOT + c]) = v0;
            *reinterpret_cast<float2*>(&g_y[(size_t)(m + 8) * NTOT + c]) = v1;
        }
    }
}

// ---------------- Precompute k.k / k.q scalars (lag-4 layout) ----------------
__device__ __forceinline__ float wsum32(float v) {
    v += __shfl_xor_sync(0xffffffffu, v, 16);
    v += __shfl_xor_sync(0xffffffffu, v, 8);
    v += __shfl_xor_sync(0xffffffffu, v, 4);
    v += __shfl_xor_sync(0xffffffffu, v, 2);
    v += __shfl_xor_sync(0xffffffffu, v, 1);
    return v;
}
__device__ __forceinline__ float d2(float2 a, float2 b) {
    return fmaf(a.x, b.x, a.y * b.y);
}

__global__ __launch_bounds__(256, 2)
void precomp_kernel()
{
    int gw = (blockIdx.x * blockDim.x + threadIdx.x) >> 5;   // 0..32767
    int lane = threadIdx.x & 31;
    int T = gw >> 5, b = gw & 31;
    int e = lane * 2;

    const float* y = g_y;
    auto ldk = [&](int tt) -> float2 {
        return *reinterpret_cast<const float2*>(&y[(size_t)(tt * BATCH + b) * NTOT + e]);
    };
    auto ldq = [&](int tt) -> float2 {
        return *reinterpret_cast<const float2*>(&y[(size_t)(tt * BATCH + b) * NTOT + 128 + e]);
    };

    int Tp1 = T + 1 < T_STEPS ? T + 1 : T_STEPS - 1;
    int Tm1 = T - 1 >= 0 ? T - 1 : 0;
    int Tm2 = T - 2 >= 0 ? T - 2 : 0;
    int Tm3 = T - 3 >= 0 ? T - 3 : 0;

    float2 kT  = ldk(T),   qT  = ldq(T);
    float2 kp1 = ldk(Tp1), qp1 = ldq(Tp1);
    float2 km1 = ldk(Tm1), km2 = ldk(Tm2), km3 = ldk(Tm3);

    float KK2n = wsum32(d2(km1, kp1));
    float KK3n = wsum32(d2(km2, kp1));
    float KK4n = wsum32(d2(km3, kp1));
    float KK1  = wsum32(d2(km1, kT));
    float KQ2n = wsum32(d2(km1, qp1));
    float KQ3n = wsum32(d2(km2, qp1));
    float KQ4n = wsum32(d2(km3, qp1));
    float KQ1  = wsum32(d2(km1, qT));
    float KQ0  = wsum32(d2(kT,  qT));

    if (lane == 0) {
        float* p = &g_pc[(size_t)gw * 12];
        *reinterpret_cast<float4*>(p)     = make_float4(KK2n, KK3n, KK4n, KK1);
        *reinterpret_cast<float4*>(p + 4) = make_float4(KQ2n, KQ3n, KQ4n, KQ1);
        *reinterpret_cast<float4*>(p + 8) = make_float4(KQ0, 0.f, 0.f, 0.f);
    }
}

// ---------------- Scan (R6 version — best measured) ----------------
#define SLOT_F 176
#define RINGS  32
#define FIELDS 43

__device__ __forceinline__ float bfly8(float v) {
    v += __shfl_xor_sync(0xffffffffu, v, 4);
    v += __shfl_xor_sync(0xffffffffu, v, 2);
    v += __shfl_xor_sync(0xffffffffu, v, 1);
    return v;
}
__device__ __forceinline__ float dot8(float4 a0, float4 a1, float4 b0, float4 b1) {
    float p = a0.x * b0.x;
    p = fmaf(a0.y, b0.y, p); p = fmaf(a0.z, b0.z, p); p = fmaf(a0.w, b0.w, p);
    p = fmaf(a1.x, b1.x, p); p = fmaf(a1.y, b1.y, p);
    p = fmaf(a1.z, b1.z, p); p = fmaf(a1.w, b1.w, p);
    return p;
}
__device__ __forceinline__ float fsig(float z) {
    return __fdividef(1.0f, 1.0f + __expf(-z));
}

__global__ __launch_bounds__(128, 1)
void scan_kernel(const float* __restrict__ S0,
                 const float* __restrict__ d_alpha,
                 const float* __restrict__ b_alpha,
                 float* __restrict__ out)
{
    __shared__ float sm[RINGS * SLOT_F];

    const int tid  = threadIdx.x;
    const int b    = blockIdx.y;
    const int i0   = blockIdx.x * 16;
    const int lane = tid & 31;
    const int w    = tid >> 5;
    const int r    = lane >> 3;
    const int j8   = lane & 7;
    const int i    = i0 + w * 4 + r;
    const int c0   = j8 * 8;
    const int il   = i - i0;

    const float* dsrc[3];
    int dstride[3], ddst[3], dtl[3];
    bool dvalid[3];
#pragma unroll
    for (int l = 0; l < 3; l++) {
        int c = tid + l * 128;
        dvalid[l] = (c < 8 * FIELDS);
        int tl = c / FIELDS, f = c - tl * FIELDS;
        dtl[l] = tl;
        int srcoff, dstf;
        if (f < 32)      { srcoff = (f < 16 ? f * 4 : 128 + (f - 16) * 4); dstf = f * 4; }
        else if (f < 36) { srcoff = 64  + i0 + (f - 32) * 4; dstf = 128 + (f - 32) * 4; }
        else if (f < 40) { srcoff = 192 + i0 + (f - 36) * 4; dstf = 144 + (f - 36) * 4; }
        else             { srcoff = (f - 40) * 4;            dstf = 160 + (f - 40) * 4; }
        if (f < 40) { dsrc[l] = g_y  + (size_t)b * NTOT + srcoff; dstride[l] = BATCH * NTOT; }
        else        { dsrc[l] = g_pc + (size_t)b * 12   + srcoff; dstride[l] = BATCH * 12;  }
        ddst[l] = tl * SLOT_F + dstf;
    }
    uint32_t smb = (uint32_t)__cvta_generic_to_shared(sm);

    auto issue_group = [&](int gidx) {
#pragma unroll
        for (int l = 0; l < 3; l++) {
            if (dvalid[l]) {
                int t  = gidx * 8 + dtl[l];
                int tc = t < T_STEPS ? t : T_STEPS - 1;
                cp_async16(smb + (uint32_t)(((gidx & 3) * 8 * SLOT_F + ddst[l]) * 4),
                           dsrc[l] + (size_t)tc * dstride[l]);
            }
        }
        asm volatile("cp.async.commit_group;\n");
    };

    issue_group(0);
    issue_group(1);
    issue_group(2);

    float4 s0v = *reinterpret_cast<const float4*>(&S0[((size_t)b * NH + i) * NH + c0]);
    float4 s1v = *reinterpret_cast<const float4*>(&S0[((size_t)b * NH + i) * NH + c0 + 4]);
    const float da  = d_alpha[i];
    const float bap = b_alpha[i];

    asm volatile("cp.async.wait_group 2;\n");
    __syncthreads();

    auto K4 = [&](int t, int c) -> float4 {
        return *reinterpret_cast<const float4*>(&sm[(t & (RINGS - 1)) * SLOT_F + c]);
    };
    auto Q4 = [&](int t, int c) -> float4 {
        return *reinterpret_cast<const float4*>(&sm[(t & (RINGS - 1)) * SLOT_F + 64 + c]);
    };

    float4 kr0[8], kr1[8];
#pragma unroll
    for (int j = 0; j < 4; j++) { kr0[j] = K4(j, c0); kr1[j] = K4(j, c0 + 4); }

    float KG = bfly8(dot8(s0v, s1v, kr0[0], kr1[0]));
    float KP = bfly8(dot8(s0v, s1v, kr0[1], kr1[1]));
    float KA2, KA1;
    {
        float p2 = dot8(s0v, s1v, kr0[2], kr1[2]);
        float l1 = p2 + __shfl_xor_sync(0xffffffffu, p2, 4);
        KA2 = l1 + __shfl_xor_sync(0xffffffffu, l1, 2);
        float p3 = dot8(s0v, s1v, kr0[3], kr1[3]);
        KA1 = p3 + __shfl_xor_sync(0xffffffffu, p3, 4);
    }
    float QG = bfly8(dot8(s0v, s1v, Q4(0, c0), Q4(0, c0 + 4)));
    float QP = bfly8(dot8(s0v, s1v, Q4(1, c0), Q4(1, c0 + 4)));
    float QA2, QA1;
    {
        float p2 = dot8(s0v, s1v, Q4(2, c0), Q4(2, c0 + 4));
        float l1 = p2 + __shfl_xor_sync(0xffffffffu, p2, 4);
        QA2 = l1 + __shfl_xor_sync(0xffffffffu, l1, 2);
        float p3 = dot8(s0v, s1v, Q4(3, c0), Q4(3, c0 + 4));
        QA1 = p3 + __shfl_xor_sync(0xffffffffu, p3, 4);
    }

    float a1 = 1.0f, a2 = 1.0f, a3 = 1.0f;
    float c1 = 0.0f, c2 = 0.0f, c3 = 0.0f;

    float* __restrict__ out_bi = out + b * NH + i;

    for (int m = 0; m < T_STEPS / 8; m++) {
        asm volatile("cp.async.wait_group 1;\n");
        __syncthreads();

#pragma unroll
        for (int u = 0; u < 8; u++) {
            const int t = m * 8 + u;
            const float* sp = &sm[(t & (RINGS - 1)) * SLOT_F];

            float4 kp0 = K4(t + 4, c0), kp1 = K4(t + 4, c0 + 4);
            float4 qp0 = Q4(t + 4, c0), qp1 = Q4(t + 4, c0 + 4);
            float  vt  = sp[128 + il];
            float  axb = sp[144 + il] + bap;
            float4 pA  = *reinterpret_cast<const float4*>(&sp[160]);
            float4 pB  = *reinterpret_cast<const float4*>(&sp[164]);
            float  kq0 = sp[168];

            float pk   = dot8(s0v, s1v, kp0, kp1);
            float KA1n = pk  + __shfl_xor_sync(0xffffffffu, pk,  4);
            float KA2n = KA1 + __shfl_xor_sync(0xffffffffu, KA1, 2);
            float KPn  = KA2 + __shfl_xor_sync(0xffffffffu, KA2, 1);
            float pq   = dot8(s0v, s1v, qp0, qp1);
            float QA1n = pq  + __shfl_xor_sync(0xffffffffu, pq,  4);
            float QA2n = QA1 + __shfl_xor_sync(0xffffffffu, QA1, 2);
            float QPn  = QA2 + __shfl_xor_sync(0xffffffffu, QA2, 1);

            float rk    = fmaf(a1, KG, c1 * pA.w);
            float z     = fmaf(da, rk, axb);
            float alpha = fsig(z);
            float cc    = (1.0f - alpha) * vt;

            float N3 = fmaf(a1, QG, c1 * pB.w);
            float h  = fmaf(alpha, N3, cc * kq0);

            float gk  = fmaf(a3, KP, c3 * pA.z);
            gk        = fmaf(a2, gk, c2 * pA.y);
            float KGn = fmaf(a1, gk, c1 * pA.x);
            float gq  = fmaf(a3, QP, c3 * pB.z);
            gq        = fmaf(a2, gq, c2 * pB.y);
            float QGn = fmaf(a1, gq, c1 * pB.x);

            float4 kc0 = kr0[u & 7], kc1 = kr1[u & 7];
            s0v.x = fmaf(alpha, s0v.x, cc * kc0.x);
            s0v.y = fmaf(alpha, s0v.y, cc * kc0.y);
            s0v.z = fmaf(alpha, s0v.z, cc * kc0.z);
            s0v.w = fmaf(alpha, s0v.w, cc * kc0.w);
            s1v.x = fmaf(alpha, s1v.x, cc * kc1.x);
            s1v.y = fmaf(alpha, s1v.y, cc * kc1.y);
            s1v.z = fmaf(alpha, s1v.z, cc * kc1.z);
            s1v.w = fmaf(alpha, s1v.w, cc * kc1.w);
            kr0[(u + 4) & 7] = kp0; kr1[(u + 4) & 7] = kp1;

            KA1 = KA1n; KA2 = KA2n; KP = KPn; KG = KGn;
            QA1 = QA1n; QA2 = QA2n; QP = QPn; QG = QGn;
            a3 = a2; a2 = a1; a1 = alpha;
            c3 = c2; c2 = c1; c1 = cc;

            if (j8 == 0) {
                float sg = fsig(h);
                out_bi[(size_t)t * (BATCH * NH)] = h * h * sg;
            }
        }

        issue_group(m + 3);
    }

    float* sf = out + (size_t)T_STEPS * BATCH * NH;
    *reinterpret_cast<float4*>(&sf[((size_t)b * NH + i) * NH + c0])     = s0v;
    *reinterpret_cast<float4*>(&sf[((size_t)b * NH + i) * NH + c0 + 4]) = s1v;
}

extern "C" void kernel_launch(void* const* d_in, const int* in_sizes, int n_in,
                              void* d_out, int out_size)
{
    const float* x  = (const float*)d_in[0];
    const float* S0 = (const float*)d_in[1];
    const float* Wk = (const float*)d_in[2];
    const float* Wv = (const float*)d_in[3];
    const float* Wq = (const float*)d_in[4];
    const float* Wa = (const float*)d_in[5];
    const float* da = (const float*)d_in[6];
    const float* ba = (const float*)d_in[7];
    float* out = (float*)d_out;
    (void)out_size;

    cudaFuncSetAttribute(proj_gemm, cudaFuncAttributeMaxDynamicSharedMemorySize, GSMEM);

    conv_x<<<2048, 256>>>((const float4*)x);
    conv_w<<<1024, 256>>>(Wk, Wv, Wq, Wa);
    proj_gemm<<<M_TOTAL / 128, 256, GSMEM>>>();
    precomp_kernel<<<M_TOTAL / 8, 256>>>();
    scan_kernel<<<dim3(4, BATCH), 128>>>(S0, da, ba, out);
}